// round 2
// baseline (speedup 1.0000x reference)
#include <cuda_runtime.h>
#include <cuda_bf16.h>

#define WEIGHT_POSITIVE 0.1f

static constexpr int BLOCKS  = 1024;
static constexpr int THREADS = 256;

// Scratch (no device allocation allowed anywhere).
__device__ float        g_partials[BLOCKS];
__device__ unsigned int g_ticket = 0;

__device__ __forceinline__ float elem(float p, int t)
{
    float d   = p - (float)t;
    bool  mis = (p >= 0.5f) != (t == 1);
    return (mis ? (1.0f + WEIGHT_POSITIVE) : 1.0f) * d * d;
}

__device__ __forceinline__ float quad(float4 p, int4 t)
{
    return elem(p.x, t.x) + elem(p.y, t.y) + elem(p.z, t.z) + elem(p.w, t.w);
}

__global__ __launch_bounds__(THREADS)
void wmse_fused_kernel(const float4* __restrict__ pred4,
                       const int4*   __restrict__ tgt4,
                       float* __restrict__ out,
                       int n_vec, float inv_n)
{
    const int stride = gridDim.x * blockDim.x;
    int i = blockIdx.x * blockDim.x + threadIdx.x;

    float s0 = 0.0f, s1 = 0.0f, s2 = 0.0f, s3 = 0.0f;

    // Unrolled x4: 8 consecutive 16B loads issued before dependent math.
    for (; i + 3 * stride < n_vec; i += 4 * stride) {
        float4 p0 = __ldcs(&pred4[i]);
        float4 p1 = __ldcs(&pred4[i +     stride]);
        float4 p2 = __ldcs(&pred4[i + 2 * stride]);
        float4 p3 = __ldcs(&pred4[i + 3 * stride]);
        int4   t0 = __ldcs(&tgt4[i]);
        int4   t1 = __ldcs(&tgt4[i +     stride]);
        int4   t2 = __ldcs(&tgt4[i + 2 * stride]);
        int4   t3 = __ldcs(&tgt4[i + 3 * stride]);
        s0 += quad(p0, t0);
        s1 += quad(p1, t1);
        s2 += quad(p2, t2);
        s3 += quad(p3, t3);
    }
    for (; i < n_vec; i += stride)
        s0 += quad(__ldcs(&pred4[i]), __ldcs(&tgt4[i]));

    float sum = (s0 + s1) + (s2 + s3);

    // Warp reduce
    #pragma unroll
    for (int off = 16; off > 0; off >>= 1)
        sum += __shfl_down_sync(0xFFFFFFFFu, sum, off);

    __shared__ float warp_sums[THREADS / 32];
    __shared__ bool  is_last;
    int lane = threadIdx.x & 31;
    int wid  = threadIdx.x >> 5;
    if (lane == 0) warp_sums[wid] = sum;
    __syncthreads();

    if (wid == 0) {
        float s = (lane < THREADS / 32) ? warp_sums[lane] : 0.0f;
        #pragma unroll
        for (int off = 16; off > 0; off >>= 1)
            s += __shfl_down_sync(0xFFFFFFFFu, s, off);
        if (lane == 0) {
            g_partials[blockIdx.x] = s;
            __threadfence();
            unsigned int t = atomicAdd(&g_ticket, 1u);
            is_last = (t == (unsigned int)(gridDim.x - 1));
        }
    }
    __syncthreads();

    // Last block to finish sums all partials in a FIXED order -> deterministic.
    if (is_last) {
        float fs = 0.0f;
        #pragma unroll
        for (int k = threadIdx.x; k < BLOCKS; k += THREADS) {
            // volatile read: partials written by other blocks after threadfence
            fs += *((volatile float*)&g_partials[k]);
        }
        #pragma unroll
        for (int off = 16; off > 0; off >>= 1)
            fs += __shfl_down_sync(0xFFFFFFFFu, fs, off);

        if (lane == 0) warp_sums[wid] = fs;
        __syncthreads();

        if (wid == 0) {
            float s = (lane < THREADS / 32) ? warp_sums[lane] : 0.0f;
            #pragma unroll
            for (int off = 16; off > 0; off >>= 1)
                s += __shfl_down_sync(0xFFFFFFFFu, s, off);
            if (lane == 0) {
                out[0] = s * inv_n;
                g_ticket = 0;   // reset for next graph replay (deterministic)
            }
        }
    }
}

extern "C" void kernel_launch(void* const* d_in, const int* in_sizes, int n_in,
                              void* d_out, int out_size)
{
    const float* pred = (const float*)d_in[0];
    const int*   tgt  = (const int*)d_in[1];
    float*       out  = (float*)d_out;
    int n = in_sizes[0];

    int n_vec = n / 4;  // N = 2^25, divisible by 4

    wmse_fused_kernel<<<BLOCKS, THREADS>>>((const float4*)pred, (const int4*)tgt,
                                           out, n_vec, 1.0f / (float)n);
}

// round 3
// speedup vs baseline: 1.0950x; 1.0950x over previous
#include <cuda_runtime.h>
#include <cuda_bf16.h>

#define WEIGHT_POSITIVE 0.1f

static constexpr int BLOCKS  = 1024;
static constexpr int THREADS = 256;

// Scratch (no device allocation allowed anywhere).
__device__ float        g_partials[BLOCKS];
__device__ unsigned int g_ticket = 0;

__device__ __forceinline__ float elem(float p, int t)
{
    float d   = p - (float)t;
    bool  mis = (p >= 0.5f) != (t == 1);
    return (mis ? (1.0f + WEIGHT_POSITIVE) : 1.0f) * d * d;
}

__global__ __launch_bounds__(THREADS)
void wmse_fused_kernel(const float4* __restrict__ pred4,
                       const int4*   __restrict__ tgt4,
                       float* __restrict__ out,
                       int n_vec, float inv_n)
{
    const int stride = gridDim.x * blockDim.x;

    float sum = 0.0f;
    for (int i = blockIdx.x * blockDim.x + threadIdx.x; i < n_vec; i += stride) {
        float4 p = __ldg(&pred4[i]);
        int4   t = __ldg(&tgt4[i]);
        sum += elem(p.x, t.x) + elem(p.y, t.y) + elem(p.z, t.z) + elem(p.w, t.w);
    }

    // Warp reduce
    #pragma unroll
    for (int off = 16; off > 0; off >>= 1)
        sum += __shfl_down_sync(0xFFFFFFFFu, sum, off);

    __shared__ float warp_sums[THREADS / 32];
    __shared__ bool  is_last;
    int lane = threadIdx.x & 31;
    int wid  = threadIdx.x >> 5;
    if (lane == 0) warp_sums[wid] = sum;
    __syncthreads();

    if (wid == 0) {
        float s = (lane < THREADS / 32) ? warp_sums[lane] : 0.0f;
        #pragma unroll
        for (int off = 16; off > 0; off >>= 1)
            s += __shfl_down_sync(0xFFFFFFFFu, s, off);
        if (lane == 0) {
            g_partials[blockIdx.x] = s;
            __threadfence();
            unsigned int t = atomicAdd(&g_ticket, 1u);
            is_last = (t == (unsigned int)(gridDim.x - 1));
        }
    }
    __syncthreads();

    // Last block to finish sums all partials in a FIXED order -> deterministic.
    if (is_last) {
        float fs = 0.0f;
        #pragma unroll
        for (int k = threadIdx.x; k < BLOCKS; k += THREADS)
            fs += *((volatile float*)&g_partials[k]);

        #pragma unroll
        for (int off = 16; off > 0; off >>= 1)
            fs += __shfl_down_sync(0xFFFFFFFFu, fs, off);

        if (lane == 0) warp_sums[wid] = fs;
        __syncthreads();

        if (wid == 0) {
            float s = (lane < THREADS / 32) ? warp_sums[lane] : 0.0f;
            #pragma unroll
            for (int off = 16; off > 0; off >>= 1)
                s += __shfl_down_sync(0xFFFFFFFFu, s, off);
            if (lane == 0) {
                out[0] = s * inv_n;
                g_ticket = 0;   // reset for next graph replay (deterministic)
            }
        }
    }
}

extern "C" void kernel_launch(void* const* d_in, const int* in_sizes, int n_in,
                              void* d_out, int out_size)
{
    const float* pred = (const float*)d_in[0];
    const int*   tgt  = (const int*)d_in[1];
    float*       out  = (float*)d_out;
    int n = in_sizes[0];

    int n_vec = n / 4;  // N = 2^25, divisible by 4

    wmse_fused_kernel<<<BLOCKS, THREADS>>>((const float4*)pred, (const int4*)tgt,
                                           out, n_vec, 1.0f / (float)n);
}